// round 1
// baseline (speedup 1.0000x reference)
#include <cuda_runtime.h>
#include <cuda_fp16.h>
#include <cstdint>

// Problem constants (fixed shapes for this problem instance)
#define E_ 8
#define H_ 2048
#define I_ 4096
#define T_ 1024

// Scratch (allocation-free rule: __device__ globals)
__device__ __half g_xh[(size_t)E_ * T_ * H_];        // fp16 activations (32 MB)
__device__ __half g_inter[(size_t)E_ * T_ * I_];     // fp16 intermediate (64 MB)

// Signed NVFP4 e2m1 LUT: lut16[c] = (c>=8 ? -1 : 1) * {0,.5,1,1.5,2,3,4,6}[c&7]
__constant__ float c_lut[16] = {
    0.f, 0.5f, 1.f, 1.5f, 2.f, 3.f, 4.f, 6.f,
   -0.f,-0.5f,-1.f,-1.5f,-2.f,-3.f,-4.f,-6.f
};

// ---------------------------------------------------------------------------
// Kernel 0: fp32 -> fp16 activation convert (vectorized)
// ---------------------------------------------------------------------------
__global__ void convert_x_kernel(const float* __restrict__ x) {
    int i = (blockIdx.x * blockDim.x + threadIdx.x) * 4;
    float4 v = *reinterpret_cast<const float4*>(x + i);
    __half2* o = reinterpret_cast<__half2*>(g_xh + i);
    o[0] = __floats2half2_rn(v.x, v.y);
    o[1] = __floats2half2_rn(v.z, v.w);
}

// ---------------------------------------------------------------------------
// mma.sync m16n8k16 f16 -> f32 accumulate (in place)
// ---------------------------------------------------------------------------
__device__ __forceinline__ void mma16816(float& d0, float& d1, float& d2, float& d3,
                                         uint32_t a0, uint32_t a1, uint32_t a2, uint32_t a3,
                                         uint32_t b0, uint32_t b1) {
    asm volatile(
        "mma.sync.aligned.m16n8k16.row.col.f32.f16.f16.f32 "
        "{%0,%1,%2,%3},{%4,%5,%6,%7},{%8,%9},{%0,%1,%2,%3};\n"
        : "+f"(d0), "+f"(d1), "+f"(d2), "+f"(d3)
        : "r"(a0), "r"(a1), "r"(a2), "r"(a3), "r"(b0), "r"(b1));
}

__device__ __forceinline__ float silu_f(float v) {
    return v / (1.f + __expf(-v));
}

// ---------------------------------------------------------------------------
// Kernel 1: gemm1 (x @ Wgu) with inline NVFP4 dequant, fused SiLU-gate
// Block tile: BM=128 (tokens) x BN=64 (inter cols; gate col n and up col I_+n)
// BK=64. 256 threads = 8 warps in 2x4 grid; warp tile 64x16 (gate) + 64x16 (up).
// ---------------------------------------------------------------------------
__global__ void __launch_bounds__(256) gemm1_silu_kernel(
    const int*   __restrict__ gup,     // [E, H/2, 2I] int32 (1 byte each)
    const float* __restrict__ gus,     // [E, H/16, 2I]
    const float* __restrict__ pgs)     // scalar gscale
{
    const int e   = blockIdx.z;
    const int bm0 = blockIdx.y * 128;
    const int n0  = blockIdx.x * 64;
    const float gscale = __ldg(pgs);

    const int tid  = threadIdx.x;
    const int lane = tid & 31;
    const int wid  = tid >> 5;
    const int g    = lane >> 2;     // group id 0..7
    const int tg   = lane & 3;      // thread-in-group 0..3
    const int wm   = wid & 1;       // 0..1 (64 rows each)
    const int wn   = wid >> 1;      // 0..3 (16 cols each)

    __shared__ __half As[128 * 72];
    __shared__ __half Bg[64 * 72];
    __shared__ __half Bu[64 * 72];
    __shared__ float  s_lut[16];
    if (tid < 16) s_lut[tid] = c_lut[tid];
    __syncthreads();

    float accg[4][2][4];
    float accu[4][2][4];
#pragma unroll
    for (int a = 0; a < 4; a++)
#pragma unroll
        for (int b = 0; b < 2; b++)
#pragma unroll
            for (int c = 0; c < 4; c++) { accg[a][b][c] = 0.f; accu[a][b][c] = 0.f; }

    // A loader: 128 rows x 64 halves; 2 threads/row, 32 halves (4x uint4) each
    const int arow = tid >> 1;
    const int aseg = (tid & 1) * 32;
    const __half* xg = g_xh + (size_t)(e * T_ + bm0 + arow) * H_;

    // B loader: 32 packed rows x 64 cols; thread -> col bc, 8 rows starting prb*8
    const int bc  = tid & 63;
    const int prb = tid >> 6;   // 0..3

    for (int k0 = 0; k0 < H_; k0 += 64) {
        // ---- stage A tile ----
        {
            const uint4* src = reinterpret_cast<const uint4*>(xg + k0 + aseg);
            uint4* dst = reinterpret_cast<uint4*>(As + arow * 72 + aseg);
#pragma unroll
            for (int j = 0; j < 4; j++) dst[j] = src[j];
        }
        // ---- stage B tiles (dequant gate + up) ----
        {
            const int kb = (k0 >> 4) + prb;  // scale block constant across j (pr/8 == prb)
            const size_t sidx = ((size_t)(e * 128 + kb)) * (2 * I_) + (n0 + bc);
            const float sg = __ldg(gus + sidx)      * gscale;
            const float su = __ldg(gus + sidx + I_) * gscale;
            const size_t pbase = ((size_t)(e * (H_ / 2) + (k0 >> 1) + prb * 8)) * (2 * I_) + (n0 + bc);
#pragma unroll
            for (int j = 0; j < 8; j++) {
                const int vg = __ldg(gup + pbase + (size_t)j * (2 * I_));
                const int vu = __ldg(gup + pbase + (size_t)j * (2 * I_) + I_);
                const int pr = prb * 8 + j;
                __half2 wg = __floats2half2_rn(s_lut[vg & 15] * sg, s_lut[(vg >> 4) & 15] * sg);
                __half2 wu = __floats2half2_rn(s_lut[vu & 15] * su, s_lut[(vu >> 4) & 15] * su);
                *reinterpret_cast<__half2*>(Bg + bc * 72 + 2 * pr) = wg;
                *reinterpret_cast<__half2*>(Bu + bc * 72 + 2 * pr) = wu;
            }
        }
        __syncthreads();

        // ---- compute: 4 k16 steps ----
#pragma unroll
        for (int kk = 0; kk < 4; kk++) {
            const int cc = kk * 16 + 2 * tg;
            uint32_t a[4][4];
#pragma unroll
            for (int mi = 0; mi < 4; mi++) {
                const int r = wm * 64 + mi * 16 + g;
                a[mi][0] = *reinterpret_cast<const uint32_t*>(As + r * 72 + cc);
                a[mi][1] = *reinterpret_cast<const uint32_t*>(As + (r + 8) * 72 + cc);
                a[mi][2] = *reinterpret_cast<const uint32_t*>(As + r * 72 + cc + 8);
                a[mi][3] = *reinterpret_cast<const uint32_t*>(As + (r + 8) * 72 + cc + 8);
            }
#pragma unroll
            for (int ni = 0; ni < 2; ni++) {
                const int nb = wn * 16 + ni * 8 + g;
                const uint32_t bg0 = *reinterpret_cast<const uint32_t*>(Bg + nb * 72 + cc);
                const uint32_t bg1 = *reinterpret_cast<const uint32_t*>(Bg + nb * 72 + cc + 8);
                const uint32_t bu0 = *reinterpret_cast<const uint32_t*>(Bu + nb * 72 + cc);
                const uint32_t bu1 = *reinterpret_cast<const uint32_t*>(Bu + nb * 72 + cc + 8);
#pragma unroll
                for (int mi = 0; mi < 4; mi++) {
                    mma16816(accg[mi][ni][0], accg[mi][ni][1], accg[mi][ni][2], accg[mi][ni][3],
                             a[mi][0], a[mi][1], a[mi][2], a[mi][3], bg0, bg1);
                    mma16816(accu[mi][ni][0], accu[mi][ni][1], accu[mi][ni][2], accu[mi][ni][3],
                             a[mi][0], a[mi][1], a[mi][2], a[mi][3], bu0, bu1);
                }
            }
        }
        __syncthreads();
    }

    // ---- epilogue: inter = up * silu(gate), fp16 store ----
#pragma unroll
    for (int mi = 0; mi < 4; mi++) {
        const int r0 = bm0 + wm * 64 + mi * 16 + g;
#pragma unroll
        for (int ni = 0; ni < 2; ni++) {
            const int c0 = n0 + wn * 16 + ni * 8 + 2 * tg;
            const float i0 = accu[mi][ni][0] * silu_f(accg[mi][ni][0]);
            const float i1 = accu[mi][ni][1] * silu_f(accg[mi][ni][1]);
            const float i2 = accu[mi][ni][2] * silu_f(accg[mi][ni][2]);
            const float i3 = accu[mi][ni][3] * silu_f(accg[mi][ni][3]);
            *reinterpret_cast<__half2*>(g_inter + (size_t)(e * T_ + r0) * I_ + c0)
                = __floats2half2_rn(i0, i1);
            *reinterpret_cast<__half2*>(g_inter + (size_t)(e * T_ + r0 + 8) * I_ + c0)
                = __floats2half2_rn(i2, i3);
        }
    }
}

// ---------------------------------------------------------------------------
// Kernel 2: gemm2 (inter @ Wd) with inline NVFP4 dequant -> fp32 out
// Block tile: BM=128 x BN=128, BK=64. 8 warps in 2x4; warp tile 64x32.
// ---------------------------------------------------------------------------
__global__ void __launch_bounds__(256) gemm2_kernel(
    const int*   __restrict__ dpk,     // [E, I/2, H] int32
    const float* __restrict__ dsc,     // [E, I/16, H]
    const float* __restrict__ pgs,     // scalar gscale
    float*       __restrict__ out)     // [E*T, H]
{
    const int e   = blockIdx.z;
    const int bm0 = blockIdx.y * 128;
    const int n0  = blockIdx.x * 128;
    const float gscale = __ldg(pgs);

    const int tid  = threadIdx.x;
    const int lane = tid & 31;
    const int wid  = tid >> 5;
    const int g    = lane >> 2;
    const int tg   = lane & 3;
    const int wm   = wid & 1;       // 0..1
    const int wn   = wid >> 1;      // 0..3 (32 cols each)

    __shared__ __half As[128 * 72];
    __shared__ __half Bs[128 * 72];
    __shared__ float  s_lut[16];
    if (tid < 16) s_lut[tid] = c_lut[tid];
    __syncthreads();

    float acc[4][4][4];
#pragma unroll
    for (int a = 0; a < 4; a++)
#pragma unroll
        for (int b = 0; b < 4; b++)
#pragma unroll
            for (int c = 0; c < 4; c++) acc[a][b][c] = 0.f;

    const int arow = tid >> 1;
    const int aseg = (tid & 1) * 32;
    const __half* ag = g_inter + (size_t)(e * T_ + bm0 + arow) * I_;

    const int bc  = tid & 127;   // 0..127
    const int prb = tid >> 7;    // 0..1

    for (int k0 = 0; k0 < I_; k0 += 64) {
        // ---- stage A tile ----
        {
            const uint4* src = reinterpret_cast<const uint4*>(ag + k0 + aseg);
            uint4* dst = reinterpret_cast<uint4*>(As + arow * 72 + aseg);
#pragma unroll
            for (int j = 0; j < 4; j++) dst[j] = src[j];
        }
        // ---- stage B tile (dequant down proj) ----
        {
            const size_t pbase = ((size_t)(e * (I_ / 2) + (k0 >> 1) + prb * 16)) * H_ + (n0 + bc);
            float s = 0.f;
#pragma unroll
            for (int j = 0; j < 16; j++) {
                const int pr = prb * 16 + j;
                if ((j & 7) == 0) {
                    const int kb = (k0 >> 4) + (pr >> 3);
                    s = __ldg(dsc + ((size_t)(e * 256 + kb)) * H_ + (n0 + bc)) * gscale;
                }
                const int v = __ldg(dpk + pbase + (size_t)j * H_);
                *reinterpret_cast<__half2*>(Bs + bc * 72 + 2 * pr)
                    = __floats2half2_rn(s_lut[v & 15] * s, s_lut[(v >> 4) & 15] * s);
            }
        }
        __syncthreads();

        // ---- compute ----
#pragma unroll
        for (int kk = 0; kk < 4; kk++) {
            const int cc = kk * 16 + 2 * tg;
            uint32_t a[4][4];
#pragma unroll
            for (int mi = 0; mi < 4; mi++) {
                const int r = wm * 64 + mi * 16 + g;
                a[mi][0] = *reinterpret_cast<const uint32_t*>(As + r * 72 + cc);
                a[mi][1] = *reinterpret_cast<const uint32_t*>(As + (r + 8) * 72 + cc);
                a[mi][2] = *reinterpret_cast<const uint32_t*>(As + r * 72 + cc + 8);
                a[mi][3] = *reinterpret_cast<const uint32_t*>(As + (r + 8) * 72 + cc + 8);
            }
#pragma unroll
            for (int ni = 0; ni < 4; ni++) {
                const int nb = wn * 32 + ni * 8 + g;
                const uint32_t b0 = *reinterpret_cast<const uint32_t*>(Bs + nb * 72 + cc);
                const uint32_t b1 = *reinterpret_cast<const uint32_t*>(Bs + nb * 72 + cc + 8);
#pragma unroll
                for (int mi = 0; mi < 4; mi++) {
                    mma16816(acc[mi][ni][0], acc[mi][ni][1], acc[mi][ni][2], acc[mi][ni][3],
                             a[mi][0], a[mi][1], a[mi][2], a[mi][3], b0, b1);
                }
            }
        }
        __syncthreads();
    }

    // ---- epilogue: fp32 stores ----
#pragma unroll
    for (int mi = 0; mi < 4; mi++) {
        const int r0 = bm0 + wm * 64 + mi * 16 + g;
#pragma unroll
        for (int ni = 0; ni < 4; ni++) {
            const int c0 = n0 + wn * 32 + ni * 8 + 2 * tg;
            float2 v0 = make_float2(acc[mi][ni][0], acc[mi][ni][1]);
            float2 v1 = make_float2(acc[mi][ni][2], acc[mi][ni][3]);
            *reinterpret_cast<float2*>(out + (size_t)(e * T_ + r0) * H_ + c0) = v0;
            *reinterpret_cast<float2*>(out + (size_t)(e * T_ + r0 + 8) * H_ + c0) = v1;
        }
    }
}

// ---------------------------------------------------------------------------
// Launch
// ---------------------------------------------------------------------------
extern "C" void kernel_launch(void* const* d_in, const int* in_sizes, int n_in,
                              void* d_out, int out_size) {
    const float* x   = (const float*)d_in[0];  // hidden_states [E*T, H]
    const int*   gup = (const int*)  d_in[1];  // gate_up_packed
    const float* gus = (const float*)d_in[2];  // gate_up_scale
    const float* gug = (const float*)d_in[3];  // gate_up_gscale (scalar)
    const int*   dpk = (const int*)  d_in[4];  // down_packed
    const float* dsc = (const float*)d_in[5];  // down_scale
    const float* dgs = (const float*)d_in[6];  // down_gscale (scalar)
    float* out = (float*)d_out;

    convert_x_kernel<<<(E_ * T_ * H_) / 1024, 256>>>(x);
    gemm1_silu_kernel<<<dim3(I_ / 64, T_ / 128, E_), 256>>>(gup, gus, gug);
    gemm2_kernel<<<dim3(H_ / 128, T_ / 128, E_), 256>>>(dpk, dsc, dgs, out);
}